// round 1
// baseline (speedup 1.0000x reference)
#include <cuda_runtime.h>
#include <cuda_bf16.h>

#define N_NODES 100000
#define N_EDGES 1600000
#define HDIM 64
#define HC 32
#define NLAYERS 3
#define BN_EPS 1e-5f

// ---- scratch (device globals; no allocation allowed) ----
__device__ float g_h  [N_NODES * HDIM];   // layer input features
__device__ float g_hs [N_NODES * HDIM];   // (h @ W) * dinv[row]
__device__ float g_agg[N_NODES * HDIM];   // aggregation accumulator
__device__ int   g_cnt[N_NODES];          // in-degree counts
__device__ float g_dinv[N_NODES];         // (deg+1)^-1/2
__device__ float g_stats[2 * HDIM];       // per-channel sum, sumsq
__device__ float g_bn[2 * HDIM];          // per-channel scale, shift

// ---------------------------------------------------------------------------
__global__ void k_zero_cnt(int n) {
    int i = blockIdx.x * blockDim.x + threadIdx.x;
    if (i < n) g_cnt[i] = 0;
}

__global__ void k_count_deg(const int* __restrict__ dst, int e) {
    int i = blockIdx.x * blockDim.x + threadIdx.x;
    if (i < e) atomicAdd(&g_cnt[dst[i]], 1);
}

__global__ void k_dinv(int n) {
    int i = blockIdx.x * blockDim.x + threadIdx.x;
    if (i < n) g_dinv[i] = rsqrtf((float)g_cnt[i] + 1.0f);
}

// input projection: h = relu(x @ W_in + b_in), x is (N,5), W_in is (5,64)
__global__ void k_input_proj(const float* __restrict__ x,
                             const float* __restrict__ Win,
                             const float* __restrict__ bin, int n) {
    int idx = blockIdx.x * blockDim.x + threadIdx.x;
    if (idx >= n * HDIM) return;
    int node = idx >> 6;
    int c = idx & 63;
    float s = bin[c];
    const float* xr = x + node * 5;
#pragma unroll
    for (int k = 0; k < 5; k++) s = fmaf(xr[k], Win[k * HDIM + c], s);
    g_h[idx] = fmaxf(s, 0.0f);
}

// 64x64 GEMM with fused epilogue: hs = (h@W)*dinv[row]; agg = hs*dinv[row]
// tile: 64 rows x 64 cols per block, 256 threads, 4x4 register micro-tile
__global__ void k_gemm64(const float* __restrict__ W, int n) {
    __shared__ float Wsm[HDIM * HDIM];
    __shared__ float Hsm[64 * 68];   // padded stride 68 (16B aligned, no bank conflict)

    int tid = threadIdx.x;
    int node0 = blockIdx.x * 64;

    // load W (4096 floats)
#pragma unroll
    for (int i = tid; i < HDIM * HDIM; i += 256) Wsm[i] = W[i];

    // load H tile (64 rows x 64 cols) as float4
#pragma unroll
    for (int it = 0; it < 4; it++) {
        int idx = tid + it * 256;          // 0..1023
        int row = idx >> 4;                // /16
        int c4  = idx & 15;
        float4 v;
        int node = node0 + row;
        if (node < n) {
            v = *reinterpret_cast<const float4*>(&g_h[node * HDIM + c4 * 4]);
        } else {
            v = make_float4(0.f, 0.f, 0.f, 0.f);
        }
        *reinterpret_cast<float4*>(&Hsm[row * 68 + c4 * 4]) = v;
    }
    __syncthreads();

    int tx = tid & 15;   // col group (4 cols)
    int ty = tid >> 4;   // row group (4 rows)
    int c0 = tx * 4;

    float acc[4][4];
#pragma unroll
    for (int j = 0; j < 4; j++)
#pragma unroll
        for (int q = 0; q < 4; q++) acc[j][q] = 0.0f;

#pragma unroll
    for (int k = 0; k < HDIM; k++) {
        float4 w = *reinterpret_cast<const float4*>(&Wsm[k * HDIM + c0]);
#pragma unroll
        for (int j = 0; j < 4; j++) {
            float hv = Hsm[(ty * 4 + j) * 68 + k];
            acc[j][0] = fmaf(hv, w.x, acc[j][0]);
            acc[j][1] = fmaf(hv, w.y, acc[j][1]);
            acc[j][2] = fmaf(hv, w.z, acc[j][2]);
            acc[j][3] = fmaf(hv, w.w, acc[j][3]);
        }
    }

#pragma unroll
    for (int j = 0; j < 4; j++) {
        int node = node0 + ty * 4 + j;
        if (node < n) {
            float di = g_dinv[node];
            float4 o;
            o.x = acc[j][0] * di; o.y = acc[j][1] * di;
            o.z = acc[j][2] * di; o.w = acc[j][3] * di;
            *reinterpret_cast<float4*>(&g_hs[node * HDIM + c0]) = o;
            float4 a;
            a.x = o.x * di; a.y = o.y * di; a.z = o.z * di; a.w = o.w * di;
            *reinterpret_cast<float4*>(&g_agg[node * HDIM + c0]) = a;
        }
    }
}

// edge scatter: agg[dst] += hs[src] * dinv[dst]   (16 threads per edge, float4 each)
__global__ void k_scatter(const int* __restrict__ ei, int e) {
    int idx = blockIdx.x * blockDim.x + threadIdx.x;
    if (idx >= e * 16) return;
    int edge = idx >> 4;
    int p = idx & 15;
    int s = ei[edge];
    int d = ei[e + edge];
    float sc = g_dinv[d];
    float4 v = *reinterpret_cast<const float4*>(&g_hs[s * HDIM + p * 4]);
    v.x *= sc; v.y *= sc; v.z *= sc; v.w *= sc;
    float* dp = &g_agg[d * HDIM + p * 4];
    asm volatile("red.global.add.v4.f32 [%0], {%1, %2, %3, %4};"
                 :: "l"(dp), "f"(v.x), "f"(v.y), "f"(v.z), "f"(v.w)
                 : "memory");
}

__global__ void k_zero_stats() {
    int i = threadIdx.x;
    if (i < 2 * HDIM) g_stats[i] = 0.0f;
}

// column-wise sum and sumsq of g_agg
__global__ void k_stats(int n) {
    __shared__ float sb[256], sb2[256];
    int tid = threadIdx.x;
    int c = tid & 63;
    int r = blockIdx.x * 4 + (tid >> 6);
    int stride = gridDim.x * 4;
    float s = 0.f, s2 = 0.f;
    for (int row = r; row < n; row += stride) {
        float v = g_agg[row * HDIM + c];
        s += v; s2 = fmaf(v, v, s2);
    }
    sb[tid] = s; sb2[tid] = s2;
    __syncthreads();
    if (tid < 128) { sb[tid] += sb[tid + 128]; sb2[tid] += sb2[tid + 128]; }
    __syncthreads();
    if (tid < 64) {
        float a = sb[tid] + sb[tid + 64];
        float b = sb2[tid] + sb2[tid + 64];
        atomicAdd(&g_stats[tid], a);
        atomicAdd(&g_stats[HDIM + tid], b);
    }
}

// per-channel scale/shift from stats (conv_b cancels inside BN, skipped)
__global__ void k_bn_finalize(const float* __restrict__ gamma,
                              const float* __restrict__ beta, int n) {
    int c = threadIdx.x;
    if (c >= HDIM) return;
    float inv_n = 1.0f / (float)n;
    float mean = g_stats[c] * inv_n;
    float var = g_stats[HDIM + c] * inv_n - mean * mean;
    float inv = rsqrtf(var + BN_EPS);
    float scale = gamma[c] * inv;
    g_bn[c] = scale;
    g_bn[HDIM + c] = beta[c] - mean * scale;
}

__global__ void k_bn_relu(int n) {
    int idx = blockIdx.x * blockDim.x + threadIdx.x;
    if (idx >= n * HDIM) return;
    int c = idx & 63;
    float v = fmaf(g_agg[idx], g_bn[c], g_bn[HDIM + c]);
    g_h[idx] = fmaxf(v, 0.0f);
}

// classifier: out[n] = relu(h[n] @ W1 + b1) @ W2 + b2
// one warp per node, 64 nodes per block (8 warps x 8 nodes), W1 cached in smem
__global__ void k_classifier(const float* __restrict__ W1,
                             const float* __restrict__ b1,
                             const float* __restrict__ W2,
                             const float* __restrict__ b2,
                             float* __restrict__ out, int n) {
    __shared__ float W1sm[HDIM * HC];   // 2048 floats
    int tid = threadIdx.x;
#pragma unroll
    for (int i = tid; i < HDIM * HC; i += 256) W1sm[i] = W1[i];
    __syncthreads();

    int lane = tid & 31;
    int warp = tid >> 5;
    float b1v = b1[lane];
    float w2v = W2[lane];
    float b2v = b2[0];
    int base = blockIdx.x * 64 + warp * 8;

    for (int i = 0; i < 8; i++) {
        int node = base + i;
        if (node >= n) break;
        float h0 = g_h[node * HDIM + lane];
        float h1 = g_h[node * HDIM + 32 + lane];
        float acc = b1v;
#pragma unroll
        for (int k = 0; k < 32; k++)
            acc = fmaf(__shfl_sync(0xFFFFFFFFu, h0, k), W1sm[k * HC + lane], acc);
#pragma unroll
        for (int k = 0; k < 32; k++)
            acc = fmaf(__shfl_sync(0xFFFFFFFFu, h1, k), W1sm[(k + 32) * HC + lane], acc);
        float r = fmaxf(acc, 0.0f) * w2v;
#pragma unroll
        for (int off = 16; off > 0; off >>= 1)
            r += __shfl_xor_sync(0xFFFFFFFFu, r, off);
        if (lane == 0) out[node] = r + b2v;
    }
}

// ---------------------------------------------------------------------------
extern "C" void kernel_launch(void* const* d_in, const int* in_sizes, int n_in,
                              void* d_out, int out_size) {
    const float* x        = (const float*)d_in[0];
    const int*   ei       = (const int*)d_in[1];
    const float* W_in     = (const float*)d_in[2];
    const float* b_in     = (const float*)d_in[3];
    const float* conv_W   = (const float*)d_in[4];
    // d_in[5] = conv_b : cancels exactly inside BatchNorm (mean subtraction) -> unused
    const float* bn_gamma = (const float*)d_in[6];
    const float* bn_beta  = (const float*)d_in[7];
    const float* W1       = (const float*)d_in[8];
    const float* b1       = (const float*)d_in[9];
    const float* W2       = (const float*)d_in[10];
    const float* b2       = (const float*)d_in[11];
    float* out = (float*)d_out;

    int n = in_sizes[0] / 5;     // num nodes
    int e = in_sizes[1] / 2;     // num edges

    // degree -> dinv
    k_zero_cnt<<<(n + 255) / 256, 256>>>(n);
    k_count_deg<<<(e + 255) / 256, 256>>>(ei + e, e);
    k_dinv<<<(n + 255) / 256, 256>>>(n);

    // input projection
    k_input_proj<<<(n * HDIM + 255) / 256, 256>>>(x, W_in, b_in, n);

    int gemm_blocks = (n + 63) / 64;
    int scat_blocks = (e * 16 + 255) / 256;
    int nh_blocks = (n * HDIM + 255) / 256;

    for (int l = 0; l < NLAYERS; l++) {
        k_gemm64<<<gemm_blocks, 256>>>(conv_W + l * HDIM * HDIM, n);
        k_scatter<<<scat_blocks, 256>>>(ei, e);
        k_zero_stats<<<1, 128>>>();
        k_stats<<<512, 256>>>(n);
        k_bn_finalize<<<1, 64>>>(bn_gamma + l * HDIM, bn_beta + l * HDIM, n);
        k_bn_relu<<<nh_blocks, 256>>>(n);
    }

    k_classifier<<<(n + 63) / 64, 256>>>(W1, b1, W2, b2, out, n);
}

// round 2
// speedup vs baseline: 1.1352x; 1.1352x over previous
#include <cuda_runtime.h>
#include <cuda_bf16.h>

#define NMAX 100000
#define EMAX 1600000
#define HDIM 64
#define HC 32
#define NLAYERS 3
#define BN_EPS 1e-5f
#define SCAN_BLK 1024
#define SCAN_MAXB 128

// ---- scratch (device globals; no allocation allowed) ----
__device__ float g_h  [NMAX * HDIM];    // input-proj features (layer 0 input)
__device__ float g_hs [NMAX * HDIM];    // (h @ W) * dinv[row]
__device__ float g_agg[NMAX * HDIM];    // pre-BN aggregated features
__device__ int   g_cnt [NMAX];          // in-degree counts
__device__ float g_dinv[NMAX];          // (deg+1)^-1/2
__device__ int   g_row [NMAX + 1];      // CSR row pointers (by dst)
__device__ int   g_cur [NMAX];          // bucket cursors
__device__ int   g_srcs[EMAX];          // src node ids sorted by dst
__device__ int   g_bsum[SCAN_MAXB];
__device__ int   g_boff[SCAN_MAXB];
__device__ float g_stats[2 * HDIM];     // per-channel sum, sumsq
__device__ float g_bn   [2 * HDIM];     // per-channel scale, shift

// ---------------------------------------------------------------------------
__global__ void k_zero_cnt(int n) {
    int i = blockIdx.x * blockDim.x + threadIdx.x;
    if (i < n) g_cnt[i] = 0;
}

__global__ void k_count_deg(const int* __restrict__ dst, int e) {
    int i = blockIdx.x * blockDim.x + threadIdx.x;
    if (i < e) atomicAdd(&g_cnt[dst[i]], 1);
}

// dinv + zero the BN stats accumulators for layer 0
__global__ void k_dinv(int n) {
    int i = blockIdx.x * blockDim.x + threadIdx.x;
    if (i < n) g_dinv[i] = rsqrtf((float)g_cnt[i] + 1.0f);
    if (blockIdx.x == 0 && threadIdx.x < 2 * HDIM) g_stats[threadIdx.x] = 0.0f;
}

// ---- prefix scan of g_cnt -> g_row (exclusive), g_cur copy --------------
__global__ void k_scan1(int n) {
    __shared__ int sh[256];
    int tid = threadIdx.x;
    int base = blockIdx.x * SCAN_BLK;
    int s = 0;
    for (int i = tid; i < SCAN_BLK; i += 256) {
        int idx = base + i;
        if (idx < n) s += g_cnt[idx];
    }
    sh[tid] = s;
    __syncthreads();
    for (int o = 128; o > 0; o >>= 1) {
        if (tid < o) sh[tid] += sh[tid + o];
        __syncthreads();
    }
    if (tid == 0) g_bsum[blockIdx.x] = sh[0];
}

__global__ void k_scan2(int nb, int e, int n) {
    __shared__ int sh[SCAN_MAXB];
    int tid = threadIdx.x;   // 128 threads
    int v = (tid < nb) ? g_bsum[tid] : 0;
    sh[tid] = v;
    __syncthreads();
    for (int o = 1; o < SCAN_MAXB; o <<= 1) {
        int t = (tid >= o) ? sh[tid - o] : 0;
        __syncthreads();
        sh[tid] += t;
        __syncthreads();
    }
    if (tid < nb) g_boff[tid] = sh[tid] - v;   // exclusive
    if (tid == 0) g_row[n] = e;
}

__global__ void k_scan3(int n) {
    __shared__ int sh[256];
    int tid = threadIdx.x;
    int base = blockIdx.x * SCAN_BLK + tid * 4;
    int v[4];
    int mine = 0;
#pragma unroll
    for (int k = 0; k < 4; k++) {
        v[k] = (base + k < n) ? g_cnt[base + k] : 0;
        mine += v[k];
    }
    sh[tid] = mine;
    __syncthreads();
    for (int o = 1; o < 256; o <<= 1) {
        int t = (tid >= o) ? sh[tid - o] : 0;
        __syncthreads();
        sh[tid] += t;
        __syncthreads();
    }
    int off = g_boff[blockIdx.x] + sh[tid] - mine;   // exclusive within grid
#pragma unroll
    for (int k = 0; k < 4; k++) {
        int idx = base + k;
        if (idx < n) {
            g_row[idx] = off;
            g_cur[idx] = off;
            off += v[k];
        }
    }
}

// bucket scatter: counting sort of src ids keyed by dst
__global__ void k_bucket(const int* __restrict__ ei, int e) {
    int i = blockIdx.x * blockDim.x + threadIdx.x;
    if (i >= e) return;
    int s = ei[i];
    int d = ei[e + i];
    int pos = atomicAdd(&g_cur[d], 1);
    g_srcs[pos] = s;
}

// ---------------------------------------------------------------------------
// input projection: h = relu(x @ W_in + b_in), x is (N,5)
__global__ void k_input_proj(const float* __restrict__ x,
                             const float* __restrict__ Win,
                             const float* __restrict__ bin, int n) {
    int idx = blockIdx.x * blockDim.x + threadIdx.x;
    if (idx >= n * 16) return;
    int node = idx >> 4;
    int c4 = (idx & 15) * 4;
    float xr[5];
#pragma unroll
    for (int k = 0; k < 5; k++) xr[k] = x[node * 5 + k];
    float4 acc = *reinterpret_cast<const float4*>(&bin[c4]);
#pragma unroll
    for (int k = 0; k < 5; k++) {
        float4 w = *reinterpret_cast<const float4*>(&Win[k * HDIM + c4]);
        acc.x = fmaf(xr[k], w.x, acc.x);
        acc.y = fmaf(xr[k], w.y, acc.y);
        acc.z = fmaf(xr[k], w.z, acc.z);
        acc.w = fmaf(xr[k], w.w, acc.w);
    }
    acc.x = fmaxf(acc.x, 0.f); acc.y = fmaxf(acc.y, 0.f);
    acc.z = fmaxf(acc.z, 0.f); acc.w = fmaxf(acc.w, 0.f);
    *reinterpret_cast<float4*>(&g_h[node * HDIM + c4]) = acc;
}

// 64x64 GEMM; input tile = g_h (layer 0) or BN(ReLU(g_agg)) (layers 1,2);
// epilogue: g_hs = (h@W) * dinv[row]
__global__ void k_gemm64(const float* __restrict__ W, int n, int use_bn) {
    __shared__ float Wsm[HDIM * HDIM];
    __shared__ float Hsm[64 * 68];

    int tid = threadIdx.x;
    int node0 = blockIdx.x * 64;

#pragma unroll
    for (int i = tid; i < HDIM * HDIM; i += 256) Wsm[i] = W[i];

#pragma unroll
    for (int it = 0; it < 4; it++) {
        int idx = tid + it * 256;
        int row = idx >> 4;
        int c4 = idx & 15;
        float4 v = make_float4(0.f, 0.f, 0.f, 0.f);
        int node = node0 + row;
        if (node < n) {
            if (use_bn) {
                v = *reinterpret_cast<const float4*>(&g_agg[node * HDIM + c4 * 4]);
                float4 sc = *reinterpret_cast<const float4*>(&g_bn[c4 * 4]);
                float4 sf = *reinterpret_cast<const float4*>(&g_bn[HDIM + c4 * 4]);
                v.x = fmaxf(fmaf(v.x, sc.x, sf.x), 0.f);
                v.y = fmaxf(fmaf(v.y, sc.y, sf.y), 0.f);
                v.z = fmaxf(fmaf(v.z, sc.z, sf.z), 0.f);
                v.w = fmaxf(fmaf(v.w, sc.w, sf.w), 0.f);
            } else {
                v = *reinterpret_cast<const float4*>(&g_h[node * HDIM + c4 * 4]);
            }
        }
        *reinterpret_cast<float4*>(&Hsm[row * 68 + c4 * 4]) = v;
    }
    __syncthreads();

    int tx = tid & 15;
    int ty = tid >> 4;
    int c0 = tx * 4;

    float acc[4][4];
#pragma unroll
    for (int j = 0; j < 4; j++)
#pragma unroll
        for (int q = 0; q < 4; q++) acc[j][q] = 0.0f;

#pragma unroll
    for (int k = 0; k < HDIM; k++) {
        float4 w = *reinterpret_cast<const float4*>(&Wsm[k * HDIM + c0]);
#pragma unroll
        for (int j = 0; j < 4; j++) {
            float hv = Hsm[(ty * 4 + j) * 68 + k];
            acc[j][0] = fmaf(hv, w.x, acc[j][0]);
            acc[j][1] = fmaf(hv, w.y, acc[j][1]);
            acc[j][2] = fmaf(hv, w.z, acc[j][2]);
            acc[j][3] = fmaf(hv, w.w, acc[j][3]);
        }
    }

#pragma unroll
    for (int j = 0; j < 4; j++) {
        int node = node0 + ty * 4 + j;
        if (node < n) {
            float di = g_dinv[node];
            float4 o;
            o.x = acc[j][0] * di; o.y = acc[j][1] * di;
            o.z = acc[j][2] * di; o.w = acc[j][3] * di;
            *reinterpret_cast<float4*>(&g_hs[node * HDIM + c0]) = o;
        }
    }
}

// ---------------------------------------------------------------------------
// pull-based aggregation: agg[d] = dinv[d] * (sum_{s in nbrs(d)} hs[s] + hs[d])
// also accumulates BN stats. warp handles NODES_PER_WARP consecutive nodes;
// lane covers channels (lane, lane+32).
#define AGG_WARPS 8
#define NODES_PER_WARP 8
__global__ void k_aggregate(int n) {
    __shared__ float s_sum[HDIM], s_sq[HDIM];
    int tid = threadIdx.x, lane = tid & 31, warp = tid >> 5;
    if (tid < HDIM) { s_sum[tid] = 0.f; s_sq[tid] = 0.f; }
    __syncthreads();

    float ls0 = 0.f, lq0 = 0.f, ls1 = 0.f, lq1 = 0.f;
    int node0 = (blockIdx.x * AGG_WARPS + warp) * NODES_PER_WARP;

    for (int i = 0; i < NODES_PER_WARP; i++) {
        int node = node0 + i;
        if (node >= n) break;
        int beg = g_row[node], end = g_row[node + 1];
        float a0 = 0.f, a1 = 0.f;
        int j = beg;
        for (; j + 4 <= end; j += 4) {
            int s0 = g_srcs[j], s1 = g_srcs[j + 1], s2 = g_srcs[j + 2], s3 = g_srcs[j + 3];
            float v00 = g_hs[s0 * HDIM + lane],      v01 = g_hs[s0 * HDIM + 32 + lane];
            float v10 = g_hs[s1 * HDIM + lane],      v11 = g_hs[s1 * HDIM + 32 + lane];
            float v20 = g_hs[s2 * HDIM + lane],      v21 = g_hs[s2 * HDIM + 32 + lane];
            float v30 = g_hs[s3 * HDIM + lane],      v31 = g_hs[s3 * HDIM + 32 + lane];
            a0 += (v00 + v10) + (v20 + v30);
            a1 += (v01 + v11) + (v21 + v31);
        }
        for (; j < end; j++) {
            int s = g_srcs[j];
            a0 += g_hs[s * HDIM + lane];
            a1 += g_hs[s * HDIM + 32 + lane];
        }
        float di = g_dinv[node];
        a0 = (a0 + g_hs[node * HDIM + lane]) * di;
        a1 = (a1 + g_hs[node * HDIM + 32 + lane]) * di;
        g_agg[node * HDIM + lane] = a0;
        g_agg[node * HDIM + 32 + lane] = a1;
        ls0 += a0; lq0 = fmaf(a0, a0, lq0);
        ls1 += a1; lq1 = fmaf(a1, a1, lq1);
    }

    atomicAdd(&s_sum[lane], ls0);
    atomicAdd(&s_sq[lane], lq0);
    atomicAdd(&s_sum[lane + 32], ls1);
    atomicAdd(&s_sq[lane + 32], lq1);
    __syncthreads();
    if (tid < HDIM) {
        atomicAdd(&g_stats[tid], s_sum[tid]);
        atomicAdd(&g_stats[HDIM + tid], s_sq[tid]);
    }
}

// per-channel scale/shift from stats (conv_b cancels inside BN); zero stats for next layer
__global__ void k_bn_finalize(const float* __restrict__ gamma,
                              const float* __restrict__ beta, int n) {
    int c = threadIdx.x;
    if (c >= HDIM) return;
    float inv_n = 1.0f / (float)n;
    float mean = g_stats[c] * inv_n;
    float var = g_stats[HDIM + c] * inv_n - mean * mean;
    float inv = rsqrtf(var + BN_EPS);
    float scale = gamma[c] * inv;
    g_bn[c] = scale;
    g_bn[HDIM + c] = beta[c] - mean * scale;
    g_stats[c] = 0.f;
    g_stats[HDIM + c] = 0.f;
}

// classifier with fused final BN+ReLU: out = relu(bn(agg) @ W1 + b1) @ W2 + b2
__global__ void k_classifier(const float* __restrict__ W1,
                             const float* __restrict__ b1,
                             const float* __restrict__ W2,
                             const float* __restrict__ b2,
                             float* __restrict__ out, int n) {
    __shared__ float W1sm[HDIM * HC];
    int tid = threadIdx.x;
#pragma unroll
    for (int i = tid; i < HDIM * HC; i += 256) W1sm[i] = W1[i];
    __syncthreads();

    int lane = tid & 31;
    int warp = tid >> 5;
    float b1v = b1[lane];
    float w2v = W2[lane];
    float b2v = b2[0];
    float sc0 = g_bn[lane],      sf0 = g_bn[HDIM + lane];
    float sc1 = g_bn[lane + 32], sf1 = g_bn[HDIM + lane + 32];
    int base = blockIdx.x * 64 + warp * 8;

    for (int i = 0; i < 8; i++) {
        int node = base + i;
        if (node >= n) break;
        float h0 = fmaxf(fmaf(g_agg[node * HDIM + lane],      sc0, sf0), 0.f);
        float h1 = fmaxf(fmaf(g_agg[node * HDIM + 32 + lane], sc1, sf1), 0.f);
        float acc = b1v;
#pragma unroll
        for (int k = 0; k < 32; k++)
            acc = fmaf(__shfl_sync(0xFFFFFFFFu, h0, k), W1sm[k * HC + lane], acc);
#pragma unroll
        for (int k = 0; k < 32; k++)
            acc = fmaf(__shfl_sync(0xFFFFFFFFu, h1, k), W1sm[(k + 32) * HC + lane], acc);
        float r = fmaxf(acc, 0.0f) * w2v;
#pragma unroll
        for (int off = 16; off > 0; off >>= 1)
            r += __shfl_xor_sync(0xFFFFFFFFu, r, off);
        if (lane == 0) out[node] = r + b2v;
    }
}

// ---------------------------------------------------------------------------
extern "C" void kernel_launch(void* const* d_in, const int* in_sizes, int n_in,
                              void* d_out, int out_size) {
    const float* x        = (const float*)d_in[0];
    const int*   ei       = (const int*)d_in[1];
    const float* W_in     = (const float*)d_in[2];
    const float* b_in     = (const float*)d_in[3];
    const float* conv_W   = (const float*)d_in[4];
    // d_in[5] = conv_b : cancels exactly inside BatchNorm -> unused
    const float* bn_gamma = (const float*)d_in[6];
    const float* bn_beta  = (const float*)d_in[7];
    const float* W1       = (const float*)d_in[8];
    const float* b1       = (const float*)d_in[9];
    const float* W2       = (const float*)d_in[10];
    const float* b2       = (const float*)d_in[11];
    float* out = (float*)d_out;

    int n = in_sizes[0] / 5;
    int e = in_sizes[1] / 2;
    int nb = (n + SCAN_BLK - 1) / SCAN_BLK;

    // degree -> dinv, CSR build
    k_zero_cnt<<<(n + 255) / 256, 256>>>(n);
    k_count_deg<<<(e + 255) / 256, 256>>>(ei + e, e);
    k_dinv<<<(n + 255) / 256, 256>>>(n);
    k_scan1<<<nb, 256>>>(n);
    k_scan2<<<1, SCAN_MAXB>>>(nb, e, n);
    k_scan3<<<nb, 256>>>(n);
    k_bucket<<<(e + 255) / 256, 256>>>(ei, e);

    // input projection
    k_input_proj<<<(n * 16 + 255) / 256, 256>>>(x, W_in, b_in, n);

    int gemm_blocks = (n + 63) / 64;
    int agg_blocks = (n + AGG_WARPS * NODES_PER_WARP - 1) / (AGG_WARPS * NODES_PER_WARP);

    for (int l = 0; l < NLAYERS; l++) {
        k_gemm64<<<gemm_blocks, 256>>>(conv_W + l * HDIM * HDIM, n, l > 0 ? 1 : 0);
        k_aggregate<<<agg_blocks, 256>>>(n);
        k_bn_finalize<<<1, 64>>>(bn_gamma + l * HDIM, bn_beta + l * HDIM, n);
    }

    k_classifier<<<(n + 63) / 64, 256>>>(W1, b1, W2, b2, out, n);
}

// round 3
// speedup vs baseline: 1.8815x; 1.6574x over previous
#include <cuda_runtime.h>
#include <cuda_fp16.h>

#define NMAX 100000
#define EMAX 1600000
#define HDIM 64
#define HC 32
#define NLAYERS 3
#define BN_EPS 1e-5f
#define SCAN_BLK 1024
#define SCAN_MAXB 128

// ---- scratch (device globals; no allocation allowed) ----
__device__ __half2 g_hs2[NMAX * 32];    // (h @ W) * dinv[row], packed fp16 pairs
__device__ float g_agg[NMAX * HDIM];    // pre-BN aggregated features (fp32)
__device__ int   g_cnt [NMAX];          // in-degree counts
__device__ float g_dinv[NMAX];          // (deg+1)^-1/2
__device__ int   g_row [NMAX + 1];      // CSR row pointers (by dst)
__device__ int   g_cur [NMAX];          // bucket cursors
__device__ int   g_srcs[EMAX];          // src node ids sorted by dst
__device__ int   g_bsum[SCAN_MAXB];
__device__ int   g_boff[SCAN_MAXB];
__device__ float g_stats[2 * HDIM];     // per-channel sum, sumsq
__device__ float g_bn   [2 * HDIM];     // per-channel scale, shift

// ---------------------------------------------------------------------------
__global__ void k_zero_cnt(int n) {
    int i = blockIdx.x * blockDim.x + threadIdx.x;
    if (i < n) g_cnt[i] = 0;
}

__global__ void k_count_deg(const int* __restrict__ dst, int e) {
    int i = blockIdx.x * blockDim.x + threadIdx.x;
    if (i < e) atomicAdd(&g_cnt[dst[i]], 1);
}

// fused: dinv for 4 nodes/thread + per-1024-chunk degree sums (scan level 1)
__global__ void k_deg_scan(int n) {
    __shared__ int sh[256];
    int tid = threadIdx.x;
    int base = blockIdx.x * SCAN_BLK + tid * 4;
    int s = 0;
    if (base + 4 <= n) {
        int4 c = *reinterpret_cast<const int4*>(&g_cnt[base]);
        g_dinv[base + 0] = rsqrtf((float)c.x + 1.0f);
        g_dinv[base + 1] = rsqrtf((float)c.y + 1.0f);
        g_dinv[base + 2] = rsqrtf((float)c.z + 1.0f);
        g_dinv[base + 3] = rsqrtf((float)c.w + 1.0f);
        s = c.x + c.y + c.z + c.w;
    } else {
#pragma unroll
        for (int k = 0; k < 4; k++) {
            if (base + k < n) {
                int c = g_cnt[base + k];
                g_dinv[base + k] = rsqrtf((float)c + 1.0f);
                s += c;
            }
        }
    }
    sh[tid] = s;
    __syncthreads();
    for (int o = 128; o > 0; o >>= 1) {
        if (tid < o) sh[tid] += sh[tid + o];
        __syncthreads();
    }
    if (tid == 0) g_bsum[blockIdx.x] = sh[0];
}

__global__ void k_scan2(int nb, int e, int n) {
    __shared__ int sh[SCAN_MAXB];
    int tid = threadIdx.x;   // 128 threads
    int v = (tid < nb) ? g_bsum[tid] : 0;
    sh[tid] = v;
    __syncthreads();
    for (int o = 1; o < SCAN_MAXB; o <<= 1) {
        int t = (tid >= o) ? sh[tid - o] : 0;
        __syncthreads();
        sh[tid] += t;
        __syncthreads();
    }
    if (tid < nb) g_boff[tid] = sh[tid] - v;   // exclusive
    if (tid == 0) g_row[n] = e;
    g_stats[tid] = 0.0f;   // zero BN stats (128 = 2*HDIM)
}

__global__ void k_scan3(int n) {
    __shared__ int sh[256];
    int tid = threadIdx.x;
    int base = blockIdx.x * SCAN_BLK + tid * 4;
    int v[4];
    int mine = 0;
#pragma unroll
    for (int k = 0; k < 4; k++) {
        v[k] = (base + k < n) ? g_cnt[base + k] : 0;
        mine += v[k];
    }
    sh[tid] = mine;
    __syncthreads();
    for (int o = 1; o < 256; o <<= 1) {
        int t = (tid >= o) ? sh[tid - o] : 0;
        __syncthreads();
        sh[tid] += t;
        __syncthreads();
    }
    int off = g_boff[blockIdx.x] + sh[tid] - mine;
#pragma unroll
    for (int k = 0; k < 4; k++) {
        int idx = base + k;
        if (idx < n) {
            g_row[idx] = off;
            g_cur[idx] = off;
            off += v[k];
        }
    }
}

__global__ void k_bucket(const int* __restrict__ ei, int e) {
    int i = blockIdx.x * blockDim.x + threadIdx.x;
    if (i >= e) return;
    int s = ei[i];
    int d = ei[e + i];
    int pos = atomicAdd(&g_cur[d], 1);
    g_srcs[pos] = s;
}

// ---------------------------------------------------------------------------
// 64x64 GEMM. Tile input:
//   layer 0: relu(x @ W_in + b_in) computed inline (x is N x 5)
//   layers 1,2: relu(BN(g_agg)) via precomputed scale/shift
// Epilogue: g_hs2 = half2((h@W) * dinv[row])
__global__ void k_gemm64(const float* __restrict__ W, int n, int use_bn,
                         const float* __restrict__ x,
                         const float* __restrict__ Win,
                         const float* __restrict__ bin) {
    __shared__ float Wsm[HDIM * HDIM];
    __shared__ float Hsm[64 * 68];

    int tid = threadIdx.x;
    int node0 = blockIdx.x * 64;

#pragma unroll
    for (int i = tid; i < HDIM * HDIM; i += 256) Wsm[i] = W[i];

#pragma unroll
    for (int it = 0; it < 4; it++) {
        int idx = tid + it * 256;
        int row = idx >> 4;
        int c4 = idx & 15;
        float4 v = make_float4(0.f, 0.f, 0.f, 0.f);
        int node = node0 + row;
        if (node < n) {
            if (use_bn) {
                v = *reinterpret_cast<const float4*>(&g_agg[node * HDIM + c4 * 4]);
                float4 sc = *reinterpret_cast<const float4*>(&g_bn[c4 * 4]);
                float4 sf = *reinterpret_cast<const float4*>(&g_bn[HDIM + c4 * 4]);
                v.x = fmaf(v.x, sc.x, sf.x);
                v.y = fmaf(v.y, sc.y, sf.y);
                v.z = fmaf(v.z, sc.z, sf.z);
                v.w = fmaf(v.w, sc.w, sf.w);
            } else {
                // inline input projection
                v = *reinterpret_cast<const float4*>(&bin[c4 * 4]);
#pragma unroll
                for (int k = 0; k < 5; k++) {
                    float xv = __ldg(&x[node * 5 + k]);
                    float4 w = *reinterpret_cast<const float4*>(&Win[k * HDIM + c4 * 4]);
                    v.x = fmaf(xv, w.x, v.x);
                    v.y = fmaf(xv, w.y, v.y);
                    v.z = fmaf(xv, w.z, v.z);
                    v.w = fmaf(xv, w.w, v.w);
                }
            }
            v.x = fmaxf(v.x, 0.f); v.y = fmaxf(v.y, 0.f);
            v.z = fmaxf(v.z, 0.f); v.w = fmaxf(v.w, 0.f);
        }
        *reinterpret_cast<float4*>(&Hsm[row * 68 + c4 * 4]) = v;
    }
    __syncthreads();

    int tx = tid & 15;
    int ty = tid >> 4;
    int c0 = tx * 4;

    float4 acc[4];
#pragma unroll
    for (int j = 0; j < 4; j++) acc[j] = make_float4(0.f, 0.f, 0.f, 0.f);

#pragma unroll
    for (int k4 = 0; k4 < 16; k4++) {
        float4 w0 = *reinterpret_cast<const float4*>(&Wsm[(k4 * 4 + 0) * HDIM + c0]);
        float4 w1 = *reinterpret_cast<const float4*>(&Wsm[(k4 * 4 + 1) * HDIM + c0]);
        float4 w2 = *reinterpret_cast<const float4*>(&Wsm[(k4 * 4 + 2) * HDIM + c0]);
        float4 w3 = *reinterpret_cast<const float4*>(&Wsm[(k4 * 4 + 3) * HDIM + c0]);
#pragma unroll
        for (int j = 0; j < 4; j++) {
            float4 hv = *reinterpret_cast<const float4*>(&Hsm[(ty * 4 + j) * 68 + k4 * 4]);
            acc[j].x = fmaf(hv.x, w0.x, acc[j].x);
            acc[j].y = fmaf(hv.x, w0.y, acc[j].y);
            acc[j].z = fmaf(hv.x, w0.z, acc[j].z);
            acc[j].w = fmaf(hv.x, w0.w, acc[j].w);
            acc[j].x = fmaf(hv.y, w1.x, acc[j].x);
            acc[j].y = fmaf(hv.y, w1.y, acc[j].y);
            acc[j].z = fmaf(hv.y, w1.z, acc[j].z);
            acc[j].w = fmaf(hv.y, w1.w, acc[j].w);
            acc[j].x = fmaf(hv.z, w2.x, acc[j].x);
            acc[j].y = fmaf(hv.z, w2.y, acc[j].y);
            acc[j].z = fmaf(hv.z, w2.z, acc[j].z);
            acc[j].w = fmaf(hv.z, w2.w, acc[j].w);
            acc[j].x = fmaf(hv.w, w3.x, acc[j].x);
            acc[j].y = fmaf(hv.w, w3.y, acc[j].y);
            acc[j].z = fmaf(hv.w, w3.z, acc[j].z);
            acc[j].w = fmaf(hv.w, w3.w, acc[j].w);
        }
    }

#pragma unroll
    for (int j = 0; j < 4; j++) {
        int node = node0 + ty * 4 + j;
        if (node < n) {
            float di = g_dinv[node];
            __half2 p0 = __floats2half2_rn(acc[j].x * di, acc[j].y * di);
            __half2 p1 = __floats2half2_rn(acc[j].z * di, acc[j].w * di);
            uint2 pk;
            pk.x = *reinterpret_cast<unsigned*>(&p0);
            pk.y = *reinterpret_cast<unsigned*>(&p1);
            *reinterpret_cast<uint2*>(&g_hs2[node * 32 + (c0 >> 1)]) = pk;
        }
    }
}

// ---------------------------------------------------------------------------
// pull-based aggregation: agg[d] = dinv[d] * (sum_{s in nbrs(d)} hs[s] + hs[d])
// lane owns channel pair (2*lane, 2*lane+1) -> one half2 gather per src.
#define AGG_WARPS 8
#define NODES_PER_WARP 8
__global__ void k_aggregate(int n) {
    __shared__ float s_sum[HDIM], s_sq[HDIM];
    int tid = threadIdx.x, lane = tid & 31, warp = tid >> 5;
    if (tid < HDIM) { s_sum[tid] = 0.f; s_sq[tid] = 0.f; }
    __syncthreads();

    float ls0 = 0.f, lq0 = 0.f, ls1 = 0.f, lq1 = 0.f;
    int node0 = (blockIdx.x * AGG_WARPS + warp) * NODES_PER_WARP;

    for (int i = 0; i < NODES_PER_WARP; i++) {
        int node = node0 + i;
        if (node >= n) break;
        int beg = g_row[node], end = g_row[node + 1];
        float a0 = 0.f, a1 = 0.f;
        int j = beg;
        for (; j + 8 <= end; j += 8) {
            int ss[8];
#pragma unroll
            for (int u = 0; u < 8; u++) ss[u] = g_srcs[j + u];
            float2 f[8];
#pragma unroll
            for (int u = 0; u < 8; u++)
                f[u] = __half22float2(g_hs2[ss[u] * 32 + lane]);
#pragma unroll
            for (int u = 0; u < 8; u++) { a0 += f[u].x; a1 += f[u].y; }
        }
        for (; j < end; j++) {
            float2 f = __half22float2(g_hs2[g_srcs[j] * 32 + lane]);
            a0 += f.x; a1 += f.y;
        }
        float2 self = __half22float2(g_hs2[node * 32 + lane]);
        float di = g_dinv[node];
        a0 = (a0 + self.x) * di;
        a1 = (a1 + self.y) * di;
        float2 o; o.x = a0; o.y = a1;
        *reinterpret_cast<float2*>(&g_agg[node * HDIM + 2 * lane]) = o;
        ls0 += a0; lq0 = fmaf(a0, a0, lq0);
        ls1 += a1; lq1 = fmaf(a1, a1, lq1);
    }

    atomicAdd(&s_sum[2 * lane], ls0);
    atomicAdd(&s_sq[2 * lane], lq0);
    atomicAdd(&s_sum[2 * lane + 1], ls1);
    atomicAdd(&s_sq[2 * lane + 1], lq1);
    __syncthreads();
    if (tid < HDIM) {
        atomicAdd(&g_stats[tid], s_sum[tid]);
        atomicAdd(&g_stats[HDIM + tid], s_sq[tid]);
    }
}

// per-channel scale/shift (conv_b cancels inside BN); rezero stats for next layer
__global__ void k_bn_finalize(const float* __restrict__ gamma,
                              const float* __restrict__ beta, int n) {
    int c = threadIdx.x;
    if (c >= HDIM) return;
    float inv_n = 1.0f / (float)n;
    float mean = g_stats[c] * inv_n;
    float var = g_stats[HDIM + c] * inv_n - mean * mean;
    float inv = rsqrtf(var + BN_EPS);
    float scale = gamma[c] * inv;
    g_bn[c] = scale;
    g_bn[HDIM + c] = beta[c] - mean * scale;
    g_stats[c] = 0.f;
    g_stats[HDIM + c] = 0.f;
}

// classifier with fused final BN+ReLU: out = relu(bn(agg) @ W1 + b1) @ W2 + b2
__global__ void k_classifier(const float* __restrict__ W1,
                             const float* __restrict__ b1,
                             const float* __restrict__ W2,
                             const float* __restrict__ b2,
                             float* __restrict__ out, int n) {
    __shared__ float W1sm[HDIM * HC];
    int tid = threadIdx.x;
#pragma unroll
    for (int i = tid; i < HDIM * HC; i += 256) W1sm[i] = W1[i];
    __syncthreads();

    int lane = tid & 31;
    int warp = tid >> 5;
    float b1v = b1[lane];
    float w2v = W2[lane];
    float b2v = b2[0];
    float sc0 = g_bn[lane],      sf0 = g_bn[HDIM + lane];
    float sc1 = g_bn[lane + 32], sf1 = g_bn[HDIM + lane + 32];
    int base = blockIdx.x * 64 + warp * 8;

    for (int i = 0; i < 8; i++) {
        int node = base + i;
        if (node >= n) break;
        float h0 = fmaxf(fmaf(g_agg[node * HDIM + lane],      sc0, sf0), 0.f);
        float h1 = fmaxf(fmaf(g_agg[node * HDIM + 32 + lane], sc1, sf1), 0.f);
        float acc = b1v;
#pragma unroll
        for (int k = 0; k < 32; k++)
            acc = fmaf(__shfl_sync(0xFFFFFFFFu, h0, k), W1sm[k * HC + lane], acc);
#pragma unroll
        for (int k = 0; k < 32; k++)
            acc = fmaf(__shfl_sync(0xFFFFFFFFu, h1, k), W1sm[(k + 32) * HC + lane], acc);
        float r = fmaxf(acc, 0.0f) * w2v;
#pragma unroll
        for (int off = 16; off > 0; off >>= 1)
            r += __shfl_xor_sync(0xFFFFFFFFu, r, off);
        if (lane == 0) out[node] = r + b2v;
    }
}

// ---------------------------------------------------------------------------
extern "C" void kernel_launch(void* const* d_in, const int* in_sizes, int n_in,
                              void* d_out, int out_size) {
    const float* x        = (const float*)d_in[0];
    const int*   ei       = (const int*)d_in[1];
    const float* W_in     = (const float*)d_in[2];
    const float* b_in     = (const float*)d_in[3];
    const float* conv_W   = (const float*)d_in[4];
    // d_in[5] = conv_b : cancels exactly inside BatchNorm -> unused
    const float* bn_gamma = (const float*)d_in[6];
    const float* bn_beta  = (const float*)d_in[7];
    const float* W1       = (const float*)d_in[8];
    const float* b1       = (const float*)d_in[9];
    const float* W2       = (const float*)d_in[10];
    const float* b2       = (const float*)d_in[11];
    float* out = (float*)d_out;

    int n = in_sizes[0] / 5;
    int e = in_sizes[1] / 2;
    int nb = (n + SCAN_BLK - 1) / SCAN_BLK;

    k_zero_cnt<<<(n + 255) / 256, 256>>>(n);
    k_count_deg<<<(e + 255) / 256, 256>>>(ei + e, e);
    k_deg_scan<<<nb, 256>>>(n);
    k_scan2<<<1, SCAN_MAXB>>>(nb, e, n);
    k_scan3<<<nb, 256>>>(n);
    k_bucket<<<(e + 255) / 256, 256>>>(ei, e);

    int gemm_blocks = (n + 63) / 64;
    int agg_blocks = (n + AGG_WARPS * NODES_PER_WARP - 1) / (AGG_WARPS * NODES_PER_WARP);

    for (int l = 0; l < NLAYERS; l++) {
        k_gemm64<<<gemm_blocks, 256>>>(conv_W + l * HDIM * HDIM, n, l > 0 ? 1 : 0,
                                       x, W_in, b_in);
        k_aggregate<<<agg_blocks, 256>>>(n);
        k_bn_finalize<<<1, 64>>>(bn_gamma + l * HDIM, bn_beta + l * HDIM, n);
    }

    k_classifier<<<(n + 63) / 64, 256>>>(W1, b1, W2, b2, out, n);
}

// round 5
// speedup vs baseline: 2.2388x; 1.1899x over previous
#include <cuda_runtime.h>
#include <cuda_fp16.h>

#define NMAX 100000
#define EMAX 1600000
#define HDIM 64
#define HC 32
#define NLAYERS 3
#define BN_EPS 1e-5f
#define SCAN_BLK 1024
#define SCAN_MAXB 128

// ---- scratch (device globals; no allocation allowed) ----
__device__ __half2 g_hs2[NMAX * 32];       // (h @ W) * dinv[row], fp16 pairs
__device__ float g_agg[NMAX * HDIM];       // pre-BN aggregated features (fp32)
__device__ int   g_cnt [NMAX];             // in-degree counts (left at 0 on exit)
__device__ float g_dinv[NMAX];             // (deg+1)^-1/2
__device__ int   g_row [NMAX + 1];         // CSR row pointers (by dst)
__device__ int   g_cur [NMAX];             // bucket cursors
__device__ int   g_srcs[EMAX];             // src node ids sorted by dst
__device__ volatile int g_part[SCAN_MAXB]; // lookback partials (total+1)
__device__ float g_stats[NLAYERS][2 * HDIM]; // per-layer channel sum, sumsq

static __device__ __forceinline__ unsigned s2u(const void* p) {
    return (unsigned)__cvta_generic_to_shared(p);
}

// ---------------------------------------------------------------------------
// count in-degrees; block 0 also zeroes lookback partials + BN stats
__global__ void k_count_deg(const int* __restrict__ dst, int e) {
    int i = blockIdx.x * blockDim.x + threadIdx.x;
    if (blockIdx.x == 0) {
        if (threadIdx.x < SCAN_MAXB) *(int*)&g_part[threadIdx.x] = 0;
        for (int j = threadIdx.x; j < NLAYERS * 2 * HDIM; j += 256)
            (&g_stats[0][0])[j] = 0.0f;
    }
    if (i < e) atomicAdd(&g_cnt[dst[i]], 1);
}

// fused scan: dinv + exclusive prefix (decoupled lookback) -> g_row, g_cur
__global__ void k_scan_fused(int n, int e) {
    __shared__ int sh[256];
    int tid = threadIdx.x, b = blockIdx.x;
    int base = b * SCAN_BLK + tid * 4;

    int v[4]; int mine = 0;
    if (base + 4 <= n) {
        int4 c = *reinterpret_cast<const int4*>(&g_cnt[base]);
        v[0] = c.x; v[1] = c.y; v[2] = c.z; v[3] = c.w;
        g_dinv[base + 0] = rsqrtf((float)c.x + 1.0f);
        g_dinv[base + 1] = rsqrtf((float)c.y + 1.0f);
        g_dinv[base + 2] = rsqrtf((float)c.z + 1.0f);
        g_dinv[base + 3] = rsqrtf((float)c.w + 1.0f);
        mine = c.x + c.y + c.z + c.w;
    } else {
#pragma unroll
        for (int k = 0; k < 4; k++) {
            v[k] = 0;
            if (base + k < n) {
                int c = g_cnt[base + k];
                v[k] = c;
                g_dinv[base + k] = rsqrtf((float)c + 1.0f);
                mine += c;
            }
        }
    }

    // block-wide inclusive scan of thread sums
    sh[tid] = mine;
    __syncthreads();
    for (int o = 1; o < 256; o <<= 1) {
        int t = (tid >= o) ? sh[tid - o] : 0;
        __syncthreads();
        sh[tid] += t;
        __syncthreads();
    }
    int excl = sh[tid] - mine;
    int total = sh[255];

    // publish block total, then look back at all predecessors (all resident)
    if (tid == 0) atomicExch((int*)&g_part[b], total + 1);
    int pref = 0;
    for (int i = tid; i < b; i += 256) {
        int p;
        while ((p = g_part[i]) == 0) {}
        pref += p - 1;
    }
    __syncthreads();
    sh[tid] = pref;
    __syncthreads();
    for (int o = 128; o > 0; o >>= 1) {
        if (tid < o) sh[tid] += sh[tid + o];
        __syncthreads();
    }
    int off = sh[0] + excl;

#pragma unroll
    for (int k = 0; k < 4; k++) {
        int idx = base + k;
        if (idx < n) {
            g_row[idx] = off;
            g_cur[idx] = off;
            off += v[k];
        }
    }
    if (b == 0 && tid == 0) g_row[n] = e;
}

// counting-sort bucket placement; also re-zero g_cnt for the next replay
__global__ void k_bucket(const int* __restrict__ ei, int e, int n) {
    int i = blockIdx.x * blockDim.x + threadIdx.x;
    if (i < n) g_cnt[i] = 0;
    if (i >= e) return;
    int s = ei[i];
    int d = ei[e + i];
    int pos = atomicAdd(&g_cur[d], 1);
    g_srcs[pos] = s;
}

// ---------------------------------------------------------------------------
// Tensor-core GEMM: 128 nodes x 64 cols per block, 8 warps (16 rows each).
// Tile input: layer 0 -> relu(x @ W_in + b_in) inline; layers 1,2 ->
// relu(BN(g_agg)) with scale/shift computed in-block from g_stats[layer-1].
// Epilogue: g_hs2 = half2((h@W) * dinv[row]).
#define GROWS 128
#define ASTRIDE 72   // halves; 144B rows: 16B aligned, ldmatrix conflict-free
__global__ void __launch_bounds__(256) k_gemm_mma(
    const float* __restrict__ W, int n, int layer,
    const float* __restrict__ x, const float* __restrict__ Win,
    const float* __restrict__ bin,
    const float* __restrict__ gamma, const float* __restrict__ beta) {
    __shared__ __half Asm[GROWS * ASTRIDE];
    __shared__ __half Wsm[HDIM * ASTRIDE];
    __shared__ float s_sc[HDIM], s_sf[HDIM];

    int tid = threadIdx.x;
    int node0 = blockIdx.x * GROWS;

    if (layer > 0) {
        if (tid < HDIM) {
            float inv_n = 1.0f / (float)n;
            float mean = g_stats[layer - 1][tid] * inv_n;
            float var = g_stats[layer - 1][HDIM + tid] * inv_n - mean * mean;
            float inv = rsqrtf(var + BN_EPS);
            float sc = gamma[tid] * inv;
            s_sc[tid] = sc;
            s_sf[tid] = beta[tid] - mean * sc;
        }
        __syncthreads();
    }

    // W (64x64 fp32) -> fp16 smem
    for (int i = tid; i < HDIM * HDIM / 4; i += 256) {
        float4 w = *reinterpret_cast<const float4*>(&W[i * 4]);
        int r = i >> 4;
        int c = (i * 4) & 63;
        __half2 h0 = __floats2half2_rn(w.x, w.y);
        __half2 h1 = __floats2half2_rn(w.z, w.w);
        uint2 pk;
        pk.x = *reinterpret_cast<unsigned*>(&h0);
        pk.y = *reinterpret_cast<unsigned*>(&h1);
        *reinterpret_cast<uint2*>(&Wsm[r * ASTRIDE + c]) = pk;
    }

    // A tile (128 x 64) -> fp16 smem, fused BN/relu or input-proj
#pragma unroll
    for (int it = 0; it < 8; it++) {
        int idx = tid + it * 256;       // 0..2047
        int row = idx >> 4;
        int c4 = (idx & 15) * 4;
        int node = node0 + row;
        float4 v = make_float4(0.f, 0.f, 0.f, 0.f);
        if (node < n) {
            if (layer > 0) {
                v = *reinterpret_cast<const float4*>(&g_agg[node * HDIM + c4]);
                v.x = fmaf(v.x, s_sc[c4 + 0], s_sf[c4 + 0]);
                v.y = fmaf(v.y, s_sc[c4 + 1], s_sf[c4 + 1]);
                v.z = fmaf(v.z, s_sc[c4 + 2], s_sf[c4 + 2]);
                v.w = fmaf(v.w, s_sc[c4 + 3], s_sf[c4 + 3]);
            } else {
                v = *reinterpret_cast<const float4*>(&bin[c4]);
#pragma unroll
                for (int k = 0; k < 5; k++) {
                    float xv = __ldg(&x[node * 5 + k]);
                    float4 w = *reinterpret_cast<const float4*>(&Win[k * HDIM + c4]);
                    v.x = fmaf(xv, w.x, v.x);
                    v.y = fmaf(xv, w.y, v.y);
                    v.z = fmaf(xv, w.z, v.z);
                    v.w = fmaf(xv, w.w, v.w);
                }
            }
            v.x = fmaxf(v.x, 0.f); v.y = fmaxf(v.y, 0.f);
            v.z = fmaxf(v.z, 0.f); v.w = fmaxf(v.w, 0.f);
        }
        __half2 h0 = __floats2half2_rn(v.x, v.y);
        __half2 h1 = __floats2half2_rn(v.z, v.w);
        uint2 pk;
        pk.x = *reinterpret_cast<unsigned*>(&h0);
        pk.y = *reinterpret_cast<unsigned*>(&h1);
        *reinterpret_cast<uint2*>(&Asm[row * ASTRIDE + c4]) = pk;
    }
    __syncthreads();

    int warp = tid >> 5, lane = tid & 31;
    int wrow = warp * 16;

    // A fragments for all 4 k-steps (m16k16 each)
    unsigned a[4][4];
    {
        int r = lane & 15;
        int cb = (lane >> 4) << 3;
#pragma unroll
        for (int ks = 0; ks < 4; ks++) {
            unsigned addr = s2u(&Asm[(wrow + r) * ASTRIDE + ks * 16 + cb]);
            asm volatile("ldmatrix.sync.aligned.m8n8.x4.shared.b16 {%0,%1,%2,%3}, [%4];"
                         : "=r"(a[ks][0]), "=r"(a[ks][1]), "=r"(a[ks][2]), "=r"(a[ks][3])
                         : "r"(addr));
        }
    }

    float acc[8][4];
#pragma unroll
    for (int nt = 0; nt < 8; nt++)
#pragma unroll
        for (int q = 0; q < 4; q++) acc[nt][q] = 0.0f;

#pragma unroll
    for (int nt = 0; nt < 8; nt++) {
#pragma unroll
        for (int ks = 0; ks < 4; ks++) {
            unsigned b0, b1;
            int r = lane & 15;
            unsigned baddr = s2u(&Wsm[(ks * 16 + r) * ASTRIDE + nt * 8]);
            asm volatile("ldmatrix.sync.aligned.m8n8.x2.trans.shared.b16 {%0,%1}, [%2];"
                         : "=r"(b0), "=r"(b1) : "r"(baddr));
            asm volatile(
                "mma.sync.aligned.m16n8k16.row.col.f32.f16.f16.f32 "
                "{%0,%1,%2,%3}, {%4,%5,%6,%7}, {%8,%9}, {%0,%1,%2,%3};"
                : "+f"(acc[nt][0]), "+f"(acc[nt][1]), "+f"(acc[nt][2]), "+f"(acc[nt][3])
                : "r"(a[ks][0]), "r"(a[ks][1]), "r"(a[ks][2]), "r"(a[ks][3]),
                  "r"(b0), "r"(b1));
        }
    }

    // epilogue: scale by dinv, pack fp16, store
    int gr = lane >> 2;
    int qp = lane & 3;
    int node_a = node0 + wrow + gr;
    int node_b = node_a + 8;
    float dia = (node_a < n) ? g_dinv[node_a] : 0.f;
    float dib = (node_b < n) ? g_dinv[node_b] : 0.f;
#pragma unroll
    for (int nt = 0; nt < 8; nt++) {
        if (node_a < n)
            g_hs2[node_a * 32 + nt * 4 + qp] =
                __floats2half2_rn(acc[nt][0] * dia, acc[nt][1] * dia);
        if (node_b < n)
            g_hs2[node_b * 32 + nt * 4 + qp] =
                __floats2half2_rn(acc[nt][2] * dib, acc[nt][3] * dib);
    }
}

// ---------------------------------------------------------------------------
// pull-based aggregation + BN stats into g_stats[layer]
#define AGG_WARPS 8
#define NODES_PER_WARP 8
__global__ void k_aggregate(int n, int layer) {
    __shared__ float s_sum[HDIM], s_sq[HDIM];
    int tid = threadIdx.x, lane = tid & 31, warp = tid >> 5;
    if (tid < HDIM) { s_sum[tid] = 0.f; s_sq[tid] = 0.f; }
    __syncthreads();

    float ls0 = 0.f, lq0 = 0.f, ls1 = 0.f, lq1 = 0.f;
    int node0 = (blockIdx.x * AGG_WARPS + warp) * NODES_PER_WARP;

    for (int i = 0; i < NODES_PER_WARP; i++) {
        int node = node0 + i;
        if (node >= n) break;
        int beg = g_row[node], end = g_row[node + 1];
        float a0 = 0.f, a1 = 0.f;
        int j = beg;
        for (; j + 8 <= end; j += 8) {
            int ss[8];
#pragma unroll
            for (int u = 0; u < 8; u++) ss[u] = g_srcs[j + u];
            float2 f[8];
#pragma unroll
            for (int u = 0; u < 8; u++)
                f[u] = __half22float2(g_hs2[ss[u] * 32 + lane]);
#pragma unroll
            for (int u = 0; u < 8; u++) { a0 += f[u].x; a1 += f[u].y; }
        }
        for (; j < end; j++) {
            float2 f = __half22float2(g_hs2[g_srcs[j] * 32 + lane]);
            a0 += f.x; a1 += f.y;
        }
        float2 self = __half22float2(g_hs2[node * 32 + lane]);
        float di = g_dinv[node];
        a0 = (a0 + self.x) * di;
        a1 = (a1 + self.y) * di;
        float2 o; o.x = a0; o.y = a1;
        *reinterpret_cast<float2*>(&g_agg[node * HDIM + 2 * lane]) = o;
        ls0 += a0; lq0 = fmaf(a0, a0, lq0);
        ls1 += a1; lq1 = fmaf(a1, a1, lq1);
    }

    atomicAdd(&s_sum[2 * lane], ls0);
    atomicAdd(&s_sq[2 * lane], lq0);
    atomicAdd(&s_sum[2 * lane + 1], ls1);
    atomicAdd(&s_sq[2 * lane + 1], lq1);
    __syncthreads();
    if (tid < HDIM) {
        atomicAdd(&g_stats[layer][tid], s_sum[tid]);
        atomicAdd(&g_stats[layer][HDIM + tid], s_sq[tid]);
    }
}

// ---------------------------------------------------------------------------
// classifier with in-block final BN+ReLU: out = relu(bn(agg) @ W1 + b1) @ W2 + b2
__global__ void k_classifier(const float* __restrict__ W1,
                             const float* __restrict__ b1,
                             const float* __restrict__ W2,
                             const float* __restrict__ b2,
                             const float* __restrict__ gamma,
                             const float* __restrict__ beta,
                             float* __restrict__ out, int n) {
    __shared__ float W1sm[HDIM * HC];
    __shared__ float s_sc[HDIM], s_sf[HDIM];
    int tid = threadIdx.x;
    if (tid < HDIM) {
        float inv_n = 1.0f / (float)n;
        float mean = g_stats[NLAYERS - 1][tid] * inv_n;
        float var = g_stats[NLAYERS - 1][HDIM + tid] * inv_n - mean * mean;
        float inv = rsqrtf(var + BN_EPS);
        float sc = gamma[tid] * inv;
        s_sc[tid] = sc;
        s_sf[tid] = beta[tid] - mean * sc;
    }
#pragma unroll
    for (int i = tid; i < HDIM * HC; i += 256) W1sm[i] = W1[i];
    __syncthreads();

    int lane = tid & 31;
    int warp = tid >> 5;
    float b1v = b1[lane];
    float w2v = W2[lane];
    float b2v = b2[0];
    float sc0 = s_sc[lane],      sf0 = s_sf[lane];
    float sc1 = s_sc[lane + 32], sf1 = s_sf[lane + 32];
    int base = blockIdx.x * 64 + warp * 8;

    for (int i = 0; i < 8; i++) {
        int node = base + i;
        if (node >= n) break;
        float h0 = fmaxf(fmaf(g_agg[node * HDIM + lane],      sc0, sf0), 0.f);
        float h1 = fmaxf(fmaf(g_agg[node * HDIM + 32 + lane], sc1, sf1), 0.f);
        float acc = b1v;
#pragma unroll
        for (int k = 0; k < 32; k++)
            acc = fmaf(__shfl_sync(0xFFFFFFFFu, h0, k), W1sm[k * HC + lane], acc);
#pragma unroll
        for (int k = 0; k < 32; k++)
            acc = fmaf(__shfl_sync(0xFFFFFFFFu, h1, k), W1sm[(k + 32) * HC + lane], acc);
        float r = fmaxf(acc, 0.0f) * w2v;
#pragma unroll
        for (int off = 16; off > 0; off >>= 1)
            r += __shfl_xor_sync(0xFFFFFFFFu, r, off);
        if (lane == 0) out[node] = r + b2v;
    }
}

// ---------------------------------------------------------------------------
extern "C" void kernel_launch(void* const* d_in, const int* in_sizes, int n_in,
                              void* d_out, int out_size) {
    const float* x        = (const float*)d_in[0];
    const int*   ei       = (const int*)d_in[1];
    const float* W_in     = (const float*)d_in[2];
    const float* b_in     = (const float*)d_in[3];
    const float* conv_W   = (const float*)d_in[4];
    // d_in[5] = conv_b : cancels exactly inside BatchNorm -> unused
    const float* bn_gamma = (const float*)d_in[6];
    const float* bn_beta  = (const float*)d_in[7];
    const float* W1       = (const float*)d_in[8];
    const float* b1       = (const float*)d_in[9];
    const float* W2       = (const float*)d_in[10];
    const float* b2       = (const float*)d_in[11];
    float* out = (float*)d_out;

    int n = in_sizes[0] / 5;
    int e = in_sizes[1] / 2;
    int nb = (n + SCAN_BLK - 1) / SCAN_BLK;

    k_count_deg<<<(e + 255) / 256, 256>>>(ei + e, e);
    k_scan_fused<<<nb, 256>>>(n, e);
    k_bucket<<<(e + 255) / 256, 256>>>(ei, e, n);

    int gemm_blocks = (n + GROWS - 1) / GROWS;
    int agg_blocks = (n + AGG_WARPS * NODES_PER_WARP - 1) / (AGG_WARPS * NODES_PER_WARP);

    for (int l = 0; l < NLAYERS; l++) {
        k_gemm_mma<<<gemm_blocks, 256>>>(
            conv_W + l * HDIM * HDIM, n, l, x, W_in, b_in,
            l > 0 ? bn_gamma + (l - 1) * HDIM : nullptr,
            l > 0 ? bn_beta + (l - 1) * HDIM : nullptr);
        k_aggregate<<<agg_blocks, 256>>>(n, l);
    }

    k_classifier<<<(n + 63) / 64, 256>>>(
        W1, b1, W2, b2,
        bn_gamma + (NLAYERS - 1) * HDIM, bn_beta + (NLAYERS - 1) * HDIM, out, n);
}